// round 2
// baseline (speedup 1.0000x reference)
#include <cuda_runtime.h>

// CodedNet: z[b,i,j] = sum_ch x[b,i,j,ch] * bk[(i-ch)%256, j, ch]
// x  : [32, 256, 256, 28] f32  (channel contiguous)
// bk : [256, 256, 28]     f32
// out: [32, 256, 256]     f32
//
// R2: split the 32 batches into 2 groups of 16 per block -> grid 1024,
// ~7 CTAs/SM resident (smem-limited), ~43% occ, to saturate DRAM.
// Mask gathered once per thread per block (now 2x total redundancy) —
// added L1 gather cost (~12us) stays hidden under the ~36us DRAM floor.

#define PDIM 256
#define CHN  28
#define JT   128                       // j per block
#define NBG  2                         // batch groups
#define NBPER (32 / NBG)               // 16 batches per block
#define TILE_VEC (JT * CHN / 4)        // 896 float4

__global__ __launch_bounds__(128)
void codednet_kernel(const float* __restrict__ x,
                     const float* __restrict__ bk,
                     float* __restrict__ out)
{
    __shared__ float4 sbuf[2][TILE_VEC];

    const int tid = threadIdx.x;            // 0..127 -> j within tile
    const int bx  = blockIdx.x;             // 0..1023
    const int i   = bx >> 2;                // 0..255 (row-major so same-row blocks co-schedule)
    const int jt  = (bx >> 1) & 1;
    const int bg  = bx & 1;
    const int j0  = jt * JT;
    const int j   = j0 + tid;
    const int b0  = bg * NBPER;

    // ---- start the batch-0 x prefetch FIRST so it overlaps the mask gather ----
    const float4* xv = reinterpret_cast<const float4*>(x);
    const size_t tile_off = ((size_t)i * PDIM + j0) * CHN / 4;  // float4 offset within a batch
    const size_t bstride  = (size_t)PDIM * PDIM * CHN / 4;      // float4 per batch

    float4 r[7];
    {
        const size_t off = tile_off + (size_t)b0 * bstride;
#pragma unroll
        for (int k = 0; k < 7; k++)
            r[k] = xv[off + tid + JT * k];
    }

    // ---- gather per-pixel mask column into registers (batch-invariant) ----
    float m[CHN];
#pragma unroll
    for (int ch = 0; ch < CHN; ch++) {
        int rrow = (i - ch + PDIM) & (PDIM - 1);
        m[ch] = __ldg(&bk[((size_t)rrow * PDIM + j) * CHN + ch]);
    }
    float4 mv[7];
#pragma unroll
    for (int k = 0; k < 7; k++)
        mv[k] = make_float4(m[4*k], m[4*k+1], m[4*k+2], m[4*k+3]);

    // ---- batch loop with double-buffered coalesced staging ----
    for (int b = 0; b < NBPER; b++) {
        float4* buf = sbuf[b & 1];
#pragma unroll
        for (int k = 0; k < 7; k++)
            buf[tid + JT * k] = r[k];

        __syncthreads();

        if (b + 1 < NBPER) {
            const size_t off = tile_off + (size_t)(b0 + b + 1) * bstride;
#pragma unroll
            for (int k = 0; k < 7; k++)
                r[k] = xv[off + tid + JT * k];
        }

        // thread tid owns pixel j: float4 idx tid*7+k (112B stride -> bank-conflict-free)
        const float4* cb = sbuf[b & 1];
        float acc = 0.0f;
#pragma unroll
        for (int k = 0; k < 7; k++) {
            float4 v = cb[tid * 7 + k];
            acc += v.x * mv[k].x + v.y * mv[k].y + v.z * mv[k].z + v.w * mv[k].w;
        }
        out[((size_t)(b0 + b) * PDIM + i) * PDIM + j] = acc;
        // buffer-reuse safety: next STS into this buffer happens at iter b+2,
        // ordered behind the iter b+1 __syncthreads which all threads reach
        // only after finishing this compute.
    }
}

extern "C" void kernel_launch(void* const* d_in, const int* in_sizes, int n_in,
                              void* d_out, int out_size)
{
    const float* x  = (const float*)d_in[0];
    const float* bk = (const float*)d_in[1];
    float* out = (float*)d_out;
    (void)in_sizes; (void)n_in; (void)out_size;

    codednet_kernel<<<PDIM * (PDIM / JT) * NBG, 128>>>(x, bk, out);
}

// round 3
// speedup vs baseline: 1.0590x; 1.0590x over previous
#include <cuda_runtime.h>

// CodedNet: z[b,i,j] = sum_ch x[b,i,j,ch] * bk[(i-ch)%256, j, ch]
// x  : [32, 256, 256, 28] f32 (channel contiguous)
// bk : [256, 256, 28]     f32
// out: [32, 256, 256]     f32
//
// R3: two kernels.
//  K1: materialize shifted mask, channel-major: bk_s[ch][i][j] = bk[(i-ch)%P, j, ch]
//      (coalesced stores; float4 reads). Removes the 8x-sector-amplified gather
//      from the hot loop entirely.
//  K2: streaming kernel, grid 1024 (16 batches/block), mask read as 28 fully
//      coalesced scalar LDGs (L2-resident), x staged via double-buffered SMEM.

#define PDIM 256
#define CHN  28
#define JT   128                       // j per block (main kernel)
#define NBG  2                         // batch groups
#define NBPER (32 / NBG)               // 16 batches per block
#define TILE_VEC (JT * CHN / 4)        // 896 float4

__device__ float g_bk_s[CHN * PDIM * PDIM];   // [ch][i][j], 7.34 MB scratch

// ---- K1: shift + transpose the mask ----------------------------------------
// One block per source row r; thread j owns pixel (r, j).
// bk_s[ch][(r+ch)%P][j] = bk[r][j][ch]   (<=>  bk_s[ch][i][j] = bk[(i-ch)%P][j][ch])
__global__ __launch_bounds__(PDIM)
void shift_mask_kernel(const float* __restrict__ bk)
{
    const int r = blockIdx.x;
    const int j = threadIdx.x;

    const float4* p = reinterpret_cast<const float4*>(bk + ((size_t)r * PDIM + j) * CHN);
    float v[CHN];
#pragma unroll
    for (int k = 0; k < 7; k++) {
        float4 t = p[k];
        v[4*k+0] = t.x; v[4*k+1] = t.y; v[4*k+2] = t.z; v[4*k+3] = t.w;
    }
#pragma unroll
    for (int ch = 0; ch < CHN; ch++) {
        int i = (r + ch) & (PDIM - 1);
        g_bk_s[((size_t)ch * PDIM + i) * PDIM + j] = v[ch];   // coalesced across lanes
    }
}

// ---- K2: main streaming kernel ---------------------------------------------
__global__ __launch_bounds__(128)
void codednet_kernel(const float* __restrict__ x,
                     float* __restrict__ out)
{
    __shared__ float4 sbuf[2][TILE_VEC];

    const int tid = threadIdx.x;            // 0..127 -> j within tile
    const int bx  = blockIdx.x;             // 0..1023
    const int i   = bx >> 2;                // 0..255
    const int jt  = (bx >> 1) & 1;
    const int bg  = bx & 1;
    const int j0  = jt * JT;
    const int j   = j0 + tid;
    const int b0  = bg * NBPER;

    // ---- batch-0 x prefetch first, overlaps the (cheap) mask loads ----
    const float4* xv = reinterpret_cast<const float4*>(x);
    const size_t tile_off = ((size_t)i * PDIM + j0) * CHN / 4;
    const size_t bstride  = (size_t)PDIM * PDIM * CHN / 4;

    float4 r[7];
    {
        const size_t off = tile_off + (size_t)b0 * bstride;
#pragma unroll
        for (int k = 0; k < 7; k++)
            r[k] = xv[off + tid + JT * k];
    }

    // ---- mask: 28 coalesced scalar loads, L2-resident, no amplification ----
    float m[CHN];
#pragma unroll
    for (int ch = 0; ch < CHN; ch++)
        m[ch] = __ldg(&g_bk_s[((size_t)ch * PDIM + i) * PDIM + j]);

    // ---- batch loop, double-buffered SMEM staging ----
    for (int b = 0; b < NBPER; b++) {
        float4* buf = sbuf[b & 1];
#pragma unroll
        for (int k = 0; k < 7; k++)
            buf[tid + JT * k] = r[k];

        __syncthreads();

        if (b + 1 < NBPER) {
            const size_t off = tile_off + (size_t)(b0 + b + 1) * bstride;
#pragma unroll
            for (int k = 0; k < 7; k++)
                r[k] = xv[off + tid + JT * k];
        }

        // thread tid owns pixel j: float4 idx tid*7+k (112B stride, conflict-free)
        const float4* cb = sbuf[b & 1];
        float acc = 0.0f;
#pragma unroll
        for (int k = 0; k < 7; k++) {
            float4 v = cb[tid * 7 + k];
            acc += v.x * m[4*k] + v.y * m[4*k+1] + v.z * m[4*k+2] + v.w * m[4*k+3];
        }
        out[((size_t)(b0 + b) * PDIM + i) * PDIM + j] = acc;
        // buffer-reuse safety: next STS into this buffer is at iter b+2, ordered
        // behind the iter b+1 __syncthreads.
    }
}

extern "C" void kernel_launch(void* const* d_in, const int* in_sizes, int n_in,
                              void* d_out, int out_size)
{
    const float* x  = (const float*)d_in[0];
    const float* bk = (const float*)d_in[1];
    float* out = (float*)d_out;
    (void)in_sizes; (void)n_in; (void)out_size;

    shift_mask_kernel<<<PDIM, PDIM>>>(bk);
    codednet_kernel<<<PDIM * (PDIM / JT) * NBG, 128>>>(x, out);
}

// round 4
// speedup vs baseline: 1.2925x; 1.2206x over previous
#include <cuda_runtime.h>
#include <cstdint>

// CodedNet: z[b,i,j] = sum_ch x[b,i,j,ch] * bk[(i-ch)%256, j, ch]
// x  : [32, 256, 256, 28] f32   bk : [256, 256, 28] f32 (binary {0,1})
// out: [32, 256, 256] f32
//
// R4: (1) mask compressed to bit-words W[i][j] (bit ch = shifted mask), built by
//     two tiny coalesced kernels; (2) main kernel streams x with a 5-stage
//     cp.async.bulk (TMA) pipeline + mbarrier, so DRAM demand is continuous
//     and independent of warp count.

#define PDIM   256
#define CHN    28
#define JT     128
#define NBPER  16                 // batches per block (grid = 256*2*2 = 1024)
#define STAGES 5
#define SLAB_F4    896            // float4 per 128-pixel slab (128*28/4)
#define SLAB_BYTES 14336
#define SMEM_MAIN  (STAGES * SLAB_BYTES + STAGES * 8)

__device__ uint32_t g_V[PDIM * PDIM];   // bit ch = bk[r][j][ch] != 0
__device__ uint32_t g_W[PDIM * PDIM];   // bit ch = bk[(i-ch)%P][j][ch] != 0

// ---- K0a: pack mask bits along channel (coalesced read via smem transpose) ----
__global__ __launch_bounds__(PDIM)
void pack_kernel(const float* __restrict__ bk)
{
    __shared__ float s_row[PDIM * CHN];          // 28 KB
    const int r = blockIdx.x, tid = threadIdx.x;
    const float4* src = reinterpret_cast<const float4*>(bk + (size_t)r * PDIM * CHN);
    float4* dst = reinterpret_cast<float4*>(s_row);
#pragma unroll
    for (int k = 0; k < 7; k++)
        dst[tid + PDIM * k] = src[tid + PDIM * k];       // coalesced
    __syncthreads();
    const float4* pix = reinterpret_cast<const float4*>(s_row) + tid * 7;
    uint32_t w = 0;
#pragma unroll
    for (int k = 0; k < 7; k++) {                        // LDS.128 conflict-free
        float4 v = pix[k];
        if (v.x != 0.f) w |= 1u << (4 * k + 0);
        if (v.y != 0.f) w |= 1u << (4 * k + 1);
        if (v.z != 0.f) w |= 1u << (4 * k + 2);
        if (v.w != 0.f) w |= 1u << (4 * k + 3);
    }
    g_V[r * PDIM + tid] = w;                             // coalesced
}

// ---- K0b: per-channel row shift: W[i][j] bit ch = V[(i-ch)%P][j] bit ch ----
__global__ __launch_bounds__(PDIM)
void shift_kernel()
{
    const int i = blockIdx.x, j = threadIdx.x;
    uint32_t w = 0;
#pragma unroll
    for (int ch = 0; ch < CHN; ch++)
        w |= g_V[(((i - ch) & (PDIM - 1)) * PDIM) + j] & (1u << ch);  // coalesced, L2-hit
    g_W[i * PDIM + j] = w;
}

// ---- mbarrier / bulk-copy helpers ----
__device__ __forceinline__ uint32_t smem_u32(const void* p) {
    return (uint32_t)__cvta_generic_to_shared(p);
}
__device__ __forceinline__ void mbar_init(uint32_t mb, uint32_t cnt) {
    asm volatile("mbarrier.init.shared.b64 [%0], %1;" :: "r"(mb), "r"(cnt) : "memory");
}
__device__ __forceinline__ void mbar_expect_tx(uint32_t mb, uint32_t bytes) {
    asm volatile("mbarrier.arrive.expect_tx.shared.b64 _, [%0], %1;" :: "r"(mb), "r"(bytes) : "memory");
}
__device__ __forceinline__ void bulk_g2s(uint32_t dst, const void* src, uint32_t bytes, uint32_t mb) {
    asm volatile("cp.async.bulk.shared::cluster.global.mbarrier::complete_tx::bytes [%0], [%1], %2, [%3];"
                 :: "r"(dst), "l"(src), "r"(bytes), "r"(mb) : "memory");
}
__device__ __forceinline__ void mbar_wait_parity(uint32_t mb, uint32_t parity) {
    uint32_t done;
    asm volatile(
        "{\n\t.reg .pred p;\n\t"
        "mbarrier.try_wait.parity.acquire.cta.shared::cta.b64 p, [%1], %2;\n\t"
        "selp.b32 %0, 1, 0, p;\n\t}"
        : "=r"(done) : "r"(mb), "r"(parity) : "memory");
    if (!done) {
        asm volatile(
            "{\n\t.reg .pred P1;\n\t"
            "WL_%=:\n\t"
            "mbarrier.try_wait.parity.acquire.cta.shared::cta.b64 P1, [%0], %1, 0x989680;\n\t"
            "@P1 bra.uni WD_%=;\n\t"
            "bra.uni WL_%=;\n\t"
            "WD_%=:\n\t}"
            :: "r"(mb), "r"(parity) : "memory");
    }
}

// ---- main streaming kernel ----
__global__ __launch_bounds__(128)
void codednet_kernel(const float* __restrict__ x, float* __restrict__ out)
{
    extern __shared__ __align__(16) char smem[];
    float4* xs = reinterpret_cast<float4*>(smem);                  // STAGES slabs
    const uint32_t mb0 = smem_u32(smem) + STAGES * SLAB_BYTES;     // STAGES mbarriers

    const int tid = threadIdx.x;
    const int bx  = blockIdx.x;                 // 0..1023
    const int i   = bx >> 2;
    const int j0  = ((bx >> 1) & 1) * JT;
    const int b0  = (bx & 1) * NBPER;
    const int j   = j0 + tid;

    // decode mask bits -> 7 float4 multiplier registers (exact: mask is {0,1})
    const uint32_t w = g_W[i * PDIM + j];       // one coalesced L2-resident load
    float4 mv[7];
#pragma unroll
    for (int k = 0; k < 7; k++) {
        mv[k].x = (w >> (4 * k + 0)) & 1u ? 1.f : 0.f;
        mv[k].y = (w >> (4 * k + 1)) & 1u ? 1.f : 0.f;
        mv[k].z = (w >> (4 * k + 2)) & 1u ? 1.f : 0.f;
        mv[k].w = (w >> (4 * k + 3)) & 1u ? 1.f : 0.f;
    }

    if (tid == 0) {
#pragma unroll
        for (int s = 0; s < STAGES; s++) mbar_init(mb0 + 8 * s, 1);
        asm volatile("fence.proxy.async.shared::cta;" ::: "memory");
    }
    __syncthreads();

    // gmem slab base for batch bb
    const char* gx = reinterpret_cast<const char*>(x);
    const size_t slab0 = ((size_t)i * PDIM + j0) * CHN * 4;        // bytes
    const size_t bstr  = (size_t)PDIM * PDIM * CHN * 4;            // bytes per batch

    // prologue: fill the pipeline
    if (tid == 0) {
#pragma unroll
        for (int s = 0; s < STAGES; s++) {
            mbar_expect_tx(mb0 + 8 * s, SLAB_BYTES);
            bulk_g2s(smem_u32(smem) + s * SLAB_BYTES,
                     gx + slab0 + (size_t)(b0 + s) * bstr, SLAB_BYTES, mb0 + 8 * s);
        }
    }

#pragma unroll 1
    for (int b = 0; b < NBPER; b++) {
        const int s = b % STAGES;
        const uint32_t parity = (uint32_t)(b / STAGES) & 1u;
        mbar_wait_parity(mb0 + 8 * s, parity);

        const float4* p = xs + s * SLAB_F4 + tid * 7;              // 112B stride: conflict-free
        float a0 = 0.f, a1 = 0.f, a2 = 0.f, a3 = 0.f;
#pragma unroll
        for (int k = 0; k < 7; k++) {
            float4 v = p[k];
            a0 += v.x * mv[k].x;  a1 += v.y * mv[k].y;
            a2 += v.z * mv[k].z;  a3 += v.w * mv[k].w;
        }
        out[((size_t)(b0 + b) * PDIM + i) * PDIM + j] = (a0 + a1) + (a2 + a3);

        __syncthreads();   // all threads done reading stage s -> safe to refill
        if (tid == 0 && b + STAGES < NBPER) {
            mbar_expect_tx(mb0 + 8 * s, SLAB_BYTES);
            bulk_g2s(smem_u32(smem) + s * SLAB_BYTES,
                     gx + slab0 + (size_t)(b0 + b + STAGES) * bstr, SLAB_BYTES, mb0 + 8 * s);
        }
    }
}

extern "C" void kernel_launch(void* const* d_in, const int* in_sizes, int n_in,
                              void* d_out, int out_size)
{
    const float* x  = (const float*)d_in[0];
    const float* bk = (const float*)d_in[1];
    float* out = (float*)d_out;
    (void)in_sizes; (void)n_in; (void)out_size;

    cudaFuncSetAttribute(codednet_kernel,
                         cudaFuncAttributeMaxDynamicSharedMemorySize, SMEM_MAIN);

    pack_kernel<<<PDIM, PDIM>>>(bk);
    shift_kernel<<<PDIM, PDIM>>>();
    codednet_kernel<<<PDIM * 2 * 2, 128, SMEM_MAIN>>>(x, out);
}

// round 5
// speedup vs baseline: 1.3680x; 1.0584x over previous
#include <cuda_runtime.h>
#include <cstdint>

// CodedNet: z[b,i,j] = sum_ch x[b,i,j,ch] * bk[(i-ch)%256, j, ch]
// x  : [32, 256, 256, 28] f32   bk : [256, 256, 28] f32 (binary {0,1})
// out: [32, 256, 256] f32
//
// R5: single cheap pre-pass (pack mask bits, no smem/no barrier, grid 512);
//     main kernel folds the per-channel shift into 28 coalesced L2-hit loads
//     of the packed words, and streams x via a 5-stage cp.async.bulk pipeline.

#define PDIM   256
#define CHN    28
#define JT     128
#define NBPER  16                 // batches per block (grid = 256*2*2 = 1024)
#define STAGES 5
#define SLAB_F4    896            // float4 per 128-pixel slab (128*28/4)
#define SLAB_BYTES 14336
#define SMEM_MAIN  (STAGES * SLAB_BYTES + STAGES * 8)

__device__ uint32_t g_V[PDIM * PDIM];   // bit ch = (bk[r][j][ch] != 0)

// ---- K0: pack mask bits along channel; one thread per pixel, no smem ----
__global__ __launch_bounds__(128)
void pack_kernel(const float* __restrict__ bk)
{
    const int p = blockIdx.x * 128 + threadIdx.x;     // pixel index 0..65535
    const float4* src = reinterpret_cast<const float4*>(bk) + p * 7;
    float4 v[7];
#pragma unroll
    for (int k = 0; k < 7; k++) v[k] = src[k];        // MLP=7, no barrier
    uint32_t w = 0;
#pragma unroll
    for (int k = 0; k < 7; k++) {
        if (v[k].x != 0.f) w |= 1u << (4 * k + 0);
        if (v[k].y != 0.f) w |= 1u << (4 * k + 1);
        if (v[k].z != 0.f) w |= 1u << (4 * k + 2);
        if (v[k].w != 0.f) w |= 1u << (4 * k + 3);
    }
    g_V[p] = w;                                        // coalesced
}

// ---- mbarrier / bulk-copy helpers ----
__device__ __forceinline__ uint32_t smem_u32(const void* p) {
    return (uint32_t)__cvta_generic_to_shared(p);
}
__device__ __forceinline__ void mbar_init(uint32_t mb, uint32_t cnt) {
    asm volatile("mbarrier.init.shared.b64 [%0], %1;" :: "r"(mb), "r"(cnt) : "memory");
}
__device__ __forceinline__ void mbar_expect_tx(uint32_t mb, uint32_t bytes) {
    asm volatile("mbarrier.arrive.expect_tx.shared.b64 _, [%0], %1;" :: "r"(mb), "r"(bytes) : "memory");
}
__device__ __forceinline__ void bulk_g2s(uint32_t dst, const void* src, uint32_t bytes, uint32_t mb) {
    asm volatile("cp.async.bulk.shared::cluster.global.mbarrier::complete_tx::bytes [%0], [%1], %2, [%3];"
                 :: "r"(dst), "l"(src), "r"(bytes), "r"(mb) : "memory");
}
__device__ __forceinline__ void mbar_wait_parity(uint32_t mb, uint32_t parity) {
    uint32_t done;
    asm volatile(
        "{\n\t.reg .pred p;\n\t"
        "mbarrier.try_wait.parity.acquire.cta.shared::cta.b64 p, [%1], %2;\n\t"
        "selp.b32 %0, 1, 0, p;\n\t}"
        : "=r"(done) : "r"(mb), "r"(parity) : "memory");
    if (!done) {
        asm volatile(
            "{\n\t.reg .pred P1;\n\t"
            "WL_%=:\n\t"
            "mbarrier.try_wait.parity.acquire.cta.shared::cta.b64 P1, [%0], %1, 0x989680;\n\t"
            "@P1 bra.uni WD_%=;\n\t"
            "bra.uni WL_%=;\n\t"
            "WD_%=:\n\t}"
            :: "r"(mb), "r"(parity) : "memory");
    }
}

// ---- main streaming kernel ----
__global__ __launch_bounds__(128)
void codednet_kernel(const float* __restrict__ x, float* __restrict__ out)
{
    extern __shared__ __align__(16) char smem[];
    float4* xs = reinterpret_cast<float4*>(smem);                  // STAGES slabs
    const uint32_t mb0 = smem_u32(smem) + STAGES * SLAB_BYTES;     // STAGES mbarriers

    const int tid = threadIdx.x;
    const int bx  = blockIdx.x;                 // 0..1023
    const int i   = bx >> 2;
    const int j0  = ((bx >> 1) & 1) * JT;
    const int b0  = (bx & 1) * NBPER;
    const int j   = j0 + tid;

    if (tid == 0) {
#pragma unroll
        for (int s = 0; s < STAGES; s++) mbar_init(mb0 + 8 * s, 1);
        asm volatile("fence.proxy.async.shared::cta;" ::: "memory");
    }
    __syncthreads();

    // prologue: fill the pipeline (issue TMA first, then decode mask under it)
    const char* gx = reinterpret_cast<const char*>(x);
    const size_t slab0 = ((size_t)i * PDIM + j0) * CHN * 4;        // bytes
    const size_t bstr  = (size_t)PDIM * PDIM * CHN * 4;            // bytes per batch
    if (tid == 0) {
#pragma unroll
        for (int s = 0; s < STAGES; s++) {
            mbar_expect_tx(mb0 + 8 * s, SLAB_BYTES);
            bulk_g2s(smem_u32(smem) + s * SLAB_BYTES,
                     gx + slab0 + (size_t)(b0 + s) * bstr, SLAB_BYTES, mb0 + 8 * s);
        }
    }

    // fold the per-channel shift here: bit ch of W comes from row (i-ch)%P.
    // 28 coalesced uint32 loads, L2-resident (g_V = 256 KB).
    float4 mv[7];
#pragma unroll
    for (int k = 0; k < 7; k++) {
        int c0 = 4 * k;
        uint32_t v0 = g_V[(((i - (c0 + 0)) & (PDIM - 1)) << 8) + j];
        uint32_t v1 = g_V[(((i - (c0 + 1)) & (PDIM - 1)) << 8) + j];
        uint32_t v2 = g_V[(((i - (c0 + 2)) & (PDIM - 1)) << 8) + j];
        uint32_t v3 = g_V[(((i - (c0 + 3)) & (PDIM - 1)) << 8) + j];
        mv[k].x = (v0 >> (c0 + 0)) & 1u ? 1.f : 0.f;
        mv[k].y = (v1 >> (c0 + 1)) & 1u ? 1.f : 0.f;
        mv[k].z = (v2 >> (c0 + 2)) & 1u ? 1.f : 0.f;
        mv[k].w = (v3 >> (c0 + 3)) & 1u ? 1.f : 0.f;
    }

#pragma unroll 1
    for (int b = 0; b < NBPER; b++) {
        const int s = b % STAGES;
        const uint32_t parity = (uint32_t)(b / STAGES) & 1u;
        mbar_wait_parity(mb0 + 8 * s, parity);

        const float4* p = xs + s * SLAB_F4 + tid * 7;              // 112B stride: conflict-free
        float a0 = 0.f, a1 = 0.f, a2 = 0.f, a3 = 0.f;
#pragma unroll
        for (int k = 0; k < 7; k++) {
            float4 v = p[k];
            a0 += v.x * mv[k].x;  a1 += v.y * mv[k].y;
            a2 += v.z * mv[k].z;  a3 += v.w * mv[k].w;
        }
        out[((size_t)(b0 + b) * PDIM + i) * PDIM + j] = (a0 + a1) + (a2 + a3);

        __syncthreads();   // all threads done reading stage s -> safe to refill
        if (tid == 0 && b + STAGES < NBPER) {
            mbar_expect_tx(mb0 + 8 * s, SLAB_BYTES);
            bulk_g2s(smem_u32(smem) + s * SLAB_BYTES,
                     gx + slab0 + (size_t)(b0 + b + STAGES) * bstr, SLAB_BYTES, mb0 + 8 * s);
        }
    }
}

extern "C" void kernel_launch(void* const* d_in, const int* in_sizes, int n_in,
                              void* d_out, int out_size)
{
    const float* x  = (const float*)d_in[0];
    const float* bk = (const float*)d_in[1];
    float* out = (float*)d_out;
    (void)in_sizes; (void)n_in; (void)out_size;

    cudaFuncSetAttribute(codednet_kernel,
                         cudaFuncAttributeMaxDynamicSharedMemorySize, SMEM_MAIN);

    pack_kernel<<<PDIM * PDIM / 128, 128>>>(bk);
    codednet_kernel<<<PDIM * 2 * 2, 128, SMEM_MAIN>>>(x, out);
}